// round 3
// baseline (speedup 1.0000x reference)
#include <cuda_runtime.h>

// QnnFormerVQC: literal gate-by-gate simulation of the 4-qubit, 3-layer VQC.
// One thread per batch element; 16-amplitude complex64 state in registers.
// Shared gate parameters (30 scalars) precomputed by a 1-thread prep kernel.
//
// Bit convention: qubit q <-> bit mask (8 >> q) (qubit 0 = MSB), matching the
// reference's axis ordering.
//
// NOTE on the "MCX": the reference's _apmcx indexes psi[..., 1, 1, 1] after
// moveaxis, which selects axes (c1, c2, t) == 1 and reverses the REMAINING
// axis c0 (qubit 0). Its actual effect is a swap of flattened amplitudes
// 7 (0111) <-> 15 (1111), i.e. X on qubit 0 controlled by qubits 1,2,3 —
// NOT a multi-controlled X onto qubit 3. We reproduce that behavior exactly.

#define NQ 4
#define NL 3

struct P {
    float cw[NL][NQ], sw[NL][NQ];  // cos/sin(weights/2)
    float ce[NL][NQ], se[NL][NQ];  // cos/sin(entangle_weights/2)
    float cg[NL], sg[NL];          // cos/sin(gammas/2)
    float cb[NL], sb[NL];          // cos/sin(betas/2)
};
__device__ P gp;

__global__ void prep_kernel(const float* __restrict__ w,
                            const float* __restrict__ ew,
                            const float* __restrict__ gam,
                            const float* __restrict__ bet) {
    if (threadIdx.x == 0) {
        for (int L = 0; L < NL; L++) {
            for (int q = 0; q < NQ; q++) {
                sincosf(0.5f * w[L * NQ + q],  &gp.sw[L][q], &gp.cw[L][q]);
                sincosf(0.5f * ew[L * NQ + q], &gp.se[L][q], &gp.ce[L][q]);
            }
            sincosf(0.5f * gam[L], &gp.sg[L], &gp.cg[L]);
            sincosf(0.5f * bet[L], &gp.sb[L], &gp.cb[L]);
        }
    }
}

// ---- register-level gate primitives (all loops fully unrolled) ----

// RX: a' = c*a - i*s*d ; d' = -i*s*a + c*d
__device__ __forceinline__ void apRX(float2* p, int mask, float c, float s) {
    #pragma unroll
    for (int i = 0; i < 16; i++) if (!(i & mask)) {
        int j = i | mask;
        float2 a = p[i], d = p[j];
        p[i] = make_float2(fmaf(c, a.x,  s * d.y), fmaf(c, a.y, -s * d.x));
        p[j] = make_float2(fmaf(s, a.y,  c * d.x), fmaf(-s, a.x, c * d.y));
    }
}

// RY: a' = c*a - s*d ; d' = s*a + c*d   (real matrix)
__device__ __forceinline__ void apRY(float2* p, int mask, float c, float s) {
    #pragma unroll
    for (int i = 0; i < 16; i++) if (!(i & mask)) {
        int j = i | mask;
        float2 a = p[i], d = p[j];
        p[i] = make_float2(fmaf(c, a.x, -s * d.x), fmaf(c, a.y, -s * d.y));
        p[j] = make_float2(fmaf(s, a.x,  c * d.x), fmaf(s, a.y,  c * d.y));
    }
}

// RZ: bit0 -> *(c - i s), bit1 -> *(c + i s)
__device__ __forceinline__ void apRZ(float2* p, int mask, float c, float s) {
    #pragma unroll
    for (int i = 0; i < 16; i++) {
        float ss = (i & mask) ? s : -s;
        float2 a = p[i];
        p[i] = make_float2(fmaf(c, a.x, -ss * a.y), fmaf(c, a.y, ss * a.x));
    }
}

// H: a' = (a+d)/sqrt2 ; d' = (a-d)/sqrt2
__device__ __forceinline__ void apH(float2* p, int mask) {
    const float R = 0.70710678118654752440f;
    #pragma unroll
    for (int i = 0; i < 16; i++) if (!(i & mask)) {
        int j = i | mask;
        float2 a = p[i], d = p[j];
        p[i] = make_float2((a.x + d.x) * R, (a.y + d.y) * R);
        p[j] = make_float2((a.x - d.x) * R, (a.y - d.y) * R);
    }
}

// X: swap pair
__device__ __forceinline__ void apXg(float2* p, int mask) {
    #pragma unroll
    for (int i = 0; i < 16; i++) if (!(i & mask)) {
        int j = i | mask;
        float2 t = p[i]; p[i] = p[j]; p[j] = t;
    }
}

// CX: swap target pair where control bit = 1
__device__ __forceinline__ void apCX(float2* p, int cmask, int tmask) {
    #pragma unroll
    for (int i = 0; i < 16; i++) if ((i & cmask) && !(i & tmask)) {
        int j = i | tmask;
        float2 t = p[i]; p[i] = p[j]; p[j] = t;
    }
}

// controlled-RX: apply RX on target pairs where control bit = 1
__device__ __forceinline__ void apCRX(float2* p, int cmask, int tmask,
                                      float c, float s) {
    #pragma unroll
    for (int i = 0; i < 16; i++) if ((i & cmask) && !(i & tmask)) {
        int j = i | tmask;
        float2 a = p[i], d = p[j];
        p[i] = make_float2(fmaf(c, a.x,  s * d.y), fmaf(c, a.y, -s * d.x));
        p[j] = make_float2(fmaf(s, a.y,  c * d.x), fmaf(-s, a.x, c * d.y));
    }
}

__global__ void __launch_bounds__(256) vqc_kernel(const float4* __restrict__ x,
                                                  float* __restrict__ out,
                                                  int n) {
    int b = blockIdx.x * blockDim.x + threadIdx.x;
    if (b >= n) return;

    float4 xv = x[b];

    float2 psi[16];
    #pragma unroll
    for (int i = 0; i < 16; i++) psi[i] = make_float2(0.f, 0.f);
    psi[0] = make_float2(1.f, 0.f);

    // data encoding: RY-like real rotation per qubit (constant-folds from |0..0>)
    {
        float c, s;
        __sincosf(0.5f * xv.x, &s, &c); apRY(psi, 8, c, s);
        __sincosf(0.5f * xv.y, &s, &c); apRY(psi, 4, c, s);
        __sincosf(0.5f * xv.z, &s, &c); apRY(psi, 2, c, s);
        __sincosf(0.5f * xv.w, &s, &c); apRY(psi, 1, c, s);
    }

    #pragma unroll
    for (int L = 0; L < NL; L++) {
        // RX, RY, RZ with the same weight angle, per qubit
        #pragma unroll
        for (int q = 0; q < NQ; q++) {
            float c = gp.cw[L][q], s = gp.sw[L][q];
            int mask = 8 >> q;
            apRX(psi, mask, c, s);
            apRY(psi, mask, c, s);
            apRZ(psi, mask, c, s);
        }

        // ring of controlled-RX: control q, target (q+1)%4
        #pragma unroll
        for (int q = 0; q < NQ; q++) {
            apCRX(psi, 8 >> q, 8 >> ((q + 1) & 3), gp.ce[L][q], gp.se[L][q]);
        }

        // diffuser-like block, matching reference semantics exactly:
        // H^4, X^4, H(q3), swap(7,15)  [reference's _apmcx], H(q3), X^4, H^4
        #pragma unroll
        for (int q = 0; q < NQ; q++) apH(psi, 8 >> q);
        #pragma unroll
        for (int q = 0; q < NQ; q++) apXg(psi, 8 >> q);
        apH(psi, 1);
        { float2 t = psi[7]; psi[7] = psi[15]; psi[15] = t; }  // see NOTE above
        apH(psi, 1);
        #pragma unroll
        for (int q = 0; q < NQ; q++) apXg(psi, 8 >> q);
        #pragma unroll
        for (int q = 0; q < NQ; q++) apH(psi, 8 >> q);

        // RZZ chain: CX(i,i+1); RZ(gamma) on i+1; CX(i,i+1)
        #pragma unroll
        for (int i = 0; i < NQ - 1; i++) {
            int cm = 8 >> i, tm = 8 >> (i + 1);
            apCX(psi, cm, tm);
            apRZ(psi, tm, gp.cg[L], gp.sg[L]);
            apCX(psi, cm, tm);
        }

        // RX(beta) on all qubits
        #pragma unroll
        for (int q = 0; q < NQ; q++) apRX(psi, 8 >> q, gp.cb[L], gp.sb[L]);
    }

    // measurement: Z, X, Y expectations per qubit
    float res[12];
    #pragma unroll
    for (int q = 0; q < NQ; q++) {
        int mask = 8 >> q;
        float z = 0.f, xr = 0.f, yi = 0.f;
        #pragma unroll
        for (int i = 0; i < 16; i++) {
            if (i & mask) continue;
            int j = i | mask;
            float2 a = psi[i], d = psi[j];
            z += fmaf(a.x, a.x, a.y * a.y) - fmaf(d.x, d.x, d.y * d.y);
            xr += fmaf(a.x, d.x, a.y * d.y);       // Re(conj(a)*d)
            yi += fmaf(a.x, d.y, -a.y * d.x);      // Im(conj(a)*d)
        }
        res[q]     = z;
        res[4 + q] = 2.f * xr;
        res[8 + q] = 2.f * yi;
    }

    float4* o = reinterpret_cast<float4*>(out + (size_t)b * 12);
    o[0] = make_float4(res[0], res[1], res[2],  res[3]);
    o[1] = make_float4(res[4], res[5], res[6],  res[7]);
    o[2] = make_float4(res[8], res[9], res[10], res[11]);
}

extern "C" void kernel_launch(void* const* d_in, const int* in_sizes, int n_in,
                              void* d_out, int out_size) {
    const float* x   = (const float*)d_in[0];  // (B, 4)
    const float* w   = (const float*)d_in[1];  // (3, 4)
    const float* ew  = (const float*)d_in[2];  // (3, 4)
    const float* gam = (const float*)d_in[3];  // (3,)
    const float* bet = (const float*)d_in[4];  // (3,)
    float* out = (float*)d_out;                // (B, 12)

    int n = in_sizes[0] / 4;

    prep_kernel<<<1, 32>>>(w, ew, gam, bet);
    int threads = 256;
    int blocks = (n + threads - 1) / threads;
    vqc_kernel<<<blocks, threads>>>((const float4*)x, out, n);
}

// round 4
// speedup vs baseline: 1.7132x; 1.7132x over previous
#include <cuda_runtime.h>

// QnnFormerVQC: algebraically reduced 4-qubit, 3-layer VQC, verified against
// the literal gate-by-gate oracle (round 3, rel_err 8.9e-7).
//
// Reductions (all derived from the reference's ACTUAL semantics, including
// its _apmcx which swaps amplitudes 7<->15):
//  - RZ*RY*RX(w) per (layer,qubit) precomputed into one 2x2 complex matrix U;
//    the previous layer's RX(beta) is pre-multiplied into it.
//  - The H/X/MCX diffuser block == I - 2 P1(q0) (x) P++(q1,q2) (x) P1(q3):
//    for i in {9,11,13,15}: psi_i -= (psi9+psi11+psi13+psi15)/2.
//  - CX-RZ(gamma)-CX chain == 16-entry diagonal phase table per layer.
//  - Final RX(beta2) folded into measurement: z' = cb*z + sb*y,
//    y' = cb*y - sb*z, x' = x  (full-angle beta2).
//
// Bit convention: qubit q <-> mask (8 >> q), qubit 0 = MSB.

#define NQ 4
#define NL 3

struct P {
    float2 U[NL][NQ][2][2];   // combined single-qubit matrices
    float  ce[NL][NQ], se[NL][NQ];  // cos/sin(entangle_weights/2)
    float2 diag[NL][16];      // RZZ-chain diagonal phases
    float  cb2, sb2;          // cos/sin(betas[2])  (FULL angle)
};
__device__ P gp;

__device__ __forceinline__ float2 cmulh(float2 a, float2 b) {
    return make_float2(a.x * b.x - a.y * b.y, a.x * b.y + a.y * b.x);
}
__device__ __forceinline__ float2 caddh(float2 a, float2 b) {
    return make_float2(a.x + b.x, a.y + b.y);
}

__global__ void prep_kernel(const float* __restrict__ w,
                            const float* __restrict__ ew,
                            const float* __restrict__ gam,
                            const float* __restrict__ bet) {
    if (threadIdx.x != 0) return;

    for (int L = 0; L < NL; L++) {
        for (int q = 0; q < NQ; q++) {
            float th = w[L * NQ + q];
            float c, s;
            sincosf(0.5f * th, &s, &c);
            // RX = [[c,-is],[-is,c]], RY = [[c,-s],[s,c]], RZ = diag(c-is, c+is)
            float2 RX[2][2] = {{{c, 0.f}, {0.f, -s}}, {{0.f, -s}, {c, 0.f}}};
            float2 RY[2][2] = {{{c, 0.f}, {-s, 0.f}}, {{s, 0.f}, {c, 0.f}}};
            float2 RZ[2][2] = {{{c, -s}, {0.f, 0.f}}, {{0.f, 0.f}, {c, s}}};
            float2 T[2][2], M[2][2];
            for (int i = 0; i < 2; i++)
                for (int j = 0; j < 2; j++)
                    T[i][j] = caddh(cmulh(RY[i][0], RX[0][j]),
                                    cmulh(RY[i][1], RX[1][j]));
            for (int i = 0; i < 2; i++)
                for (int j = 0; j < 2; j++)
                    M[i][j] = caddh(cmulh(RZ[i][0], T[0][j]),
                                    cmulh(RZ[i][1], T[1][j]));
            // fold previous layer's RX(beta) (applied earlier in time):
            // M_eff = M * RXb
            if (L > 0) {
                float cb, sb;
                sincosf(0.5f * bet[L - 1], &sb, &cb);
                float2 RXb[2][2] = {{{cb, 0.f}, {0.f, -sb}},
                                    {{0.f, -sb}, {cb, 0.f}}};
                float2 E[2][2];
                for (int i = 0; i < 2; i++)
                    for (int j = 0; j < 2; j++)
                        E[i][j] = caddh(cmulh(M[i][0], RXb[0][j]),
                                        cmulh(M[i][1], RXb[1][j]));
                for (int i = 0; i < 2; i++)
                    for (int j = 0; j < 2; j++)
                        M[i][j] = E[i][j];
            }
            for (int i = 0; i < 2; i++)
                for (int j = 0; j < 2; j++)
                    gp.U[L][q][i][j] = M[i][j];

            sincosf(0.5f * ew[L * NQ + q], &gp.se[L][q], &gp.ce[L][q]);
        }

        // RZZ-chain diagonal: phase = g/2 * (3 - 2k), k = # equal neighbor
        // bit pairs among (q0,q1),(q1,q2),(q2,q3)
        float g = gam[L];
        for (int idx = 0; idx < 16; idx++) {
            int k = 0;
            for (int i = 0; i < 3; i++) {
                int bi = (idx >> (3 - i)) & 1;
                int bj = (idx >> (2 - i)) & 1;
                if (bi == bj) k++;
            }
            float ang = 0.5f * g * (float)(3 - 2 * k);
            float sa, ca;
            sincosf(ang, &sa, &ca);
            gp.diag[L][idx] = make_float2(ca, sa);
        }
    }
    // full-angle beta for measurement fold
    sincosf(bet[NL - 1], &gp.sb2, &gp.cb2);
}

__global__ void __launch_bounds__(256) vqc_kernel(const float4* __restrict__ x,
                                                  float* __restrict__ out,
                                                  int n) {
    int b = blockIdx.x * blockDim.x + threadIdx.x;
    if (b >= n) return;

    float4 xv = x[b];
    float cq[4], sq[4];
    __sincosf(0.5f * xv.x, &sq[0], &cq[0]);
    __sincosf(0.5f * xv.y, &sq[1], &cq[1]);
    __sincosf(0.5f * xv.z, &sq[2], &cq[2]);
    __sincosf(0.5f * xv.w, &sq[3], &cq[3]);

    // initial product state (real): qubit q bit set -> s, clear -> c
    float2 psi[16];
    #pragma unroll
    for (int i = 0; i < 16; i++) {
        float a = ((i & 8) ? sq[0] : cq[0]) * ((i & 4) ? sq[1] : cq[1]) *
                  ((i & 2) ? sq[2] : cq[2]) * ((i & 1) ? sq[3] : cq[3]);
        psi[i] = make_float2(a, 0.f);
    }

    #pragma unroll
    for (int L = 0; L < NL; L++) {
        // combined single-qubit U (includes prev layer's RX(beta))
        #pragma unroll
        for (int q = 0; q < NQ; q++) {
            float2 u00 = gp.U[L][q][0][0], u01 = gp.U[L][q][0][1];
            float2 u10 = gp.U[L][q][1][0], u11 = gp.U[L][q][1][1];
            int mask = 8 >> q;
            #pragma unroll
            for (int i = 0; i < 16; i++) {
                if (i & mask) continue;
                int j = i | mask;
                float2 a = psi[i], d = psi[j];
                float nr, ni, mr, mi;
                nr = u00.x * a.x; nr = fmaf(-u00.y, a.y, nr);
                nr = fmaf(u01.x, d.x, nr); nr = fmaf(-u01.y, d.y, nr);
                ni = u00.x * a.y; ni = fmaf(u00.y, a.x, ni);
                ni = fmaf(u01.x, d.y, ni); ni = fmaf(u01.y, d.x, ni);
                mr = u10.x * a.x; mr = fmaf(-u10.y, a.y, mr);
                mr = fmaf(u11.x, d.x, mr); mr = fmaf(-u11.y, d.y, mr);
                mi = u10.x * a.y; mi = fmaf(u10.y, a.x, mi);
                mi = fmaf(u11.x, d.y, mi); mi = fmaf(u11.y, d.x, mi);
                psi[i] = make_float2(nr, ni);
                psi[j] = make_float2(mr, mi);
            }
        }

        // ring of controlled-RX: control q, target (q+1)%4
        #pragma unroll
        for (int q = 0; q < NQ; q++) {
            float c = gp.ce[L][q], s = gp.se[L][q];
            int cmask = 8 >> q;
            int tmask = 8 >> ((q + 1) & 3);
            #pragma unroll
            for (int i = 0; i < 16; i++) {
                if (!(i & cmask) || (i & tmask)) continue;
                int j = i | tmask;
                float2 a = psi[i], d = psi[j];
                psi[i] = make_float2(fmaf(c, a.x,  s * d.y),
                                     fmaf(c, a.y, -s * d.x));
                psi[j] = make_float2(fmaf(s, a.y,  c * d.x),
                                     fmaf(-s, a.x, c * d.y));
            }
        }

        // diffuser block: psi_i -= (psi9+psi11+psi13+psi15)/2 for i in that set
        {
            float sr = (psi[9].x + psi[11].x) + (psi[13].x + psi[15].x);
            float si = (psi[9].y + psi[11].y) + (psi[13].y + psi[15].y);
            sr *= 0.5f; si *= 0.5f;
            psi[9].x  -= sr; psi[9].y  -= si;
            psi[11].x -= sr; psi[11].y -= si;
            psi[13].x -= sr; psi[13].y -= si;
            psi[15].x -= sr; psi[15].y -= si;
        }

        // RZZ-chain diagonal phases
        #pragma unroll
        for (int i = 0; i < 16; i++) {
            float2 ph = gp.diag[L][i];
            float2 a = psi[i];
            psi[i] = make_float2(fmaf(ph.x, a.x, -ph.y * a.y),
                                 fmaf(ph.x, a.y,  ph.y * a.x));
        }
        // RX(beta_L): L<2 folded into next layer's U; L==2 folded into
        // the measurement below.
    }

    // measurement (pre final-RX), then rotate Z/Y by full-angle beta2
    float cb = gp.cb2, sb = gp.sb2;
    float res[12];
    #pragma unroll
    for (int q = 0; q < NQ; q++) {
        int mask = 8 >> q;
        float z = 0.f, xr = 0.f, yi = 0.f;
        #pragma unroll
        for (int i = 0; i < 16; i++) {
            if (i & mask) continue;
            int j = i | mask;
            float2 a = psi[i], d = psi[j];
            z += fmaf(a.x, a.x, a.y * a.y) - fmaf(d.x, d.x, d.y * d.y);
            xr += fmaf(a.x, d.x, a.y * d.y);    // Re(conj(a)*d)
            yi += fmaf(a.x, d.y, -a.y * d.x);   // Im(conj(a)*d)
        }
        float xo = 2.f * xr, yo = 2.f * yi;
        res[q]     = fmaf(cb, z, sb * yo);      // z' = cb*z + sb*y
        res[4 + q] = xo;                        // x' = x
        res[8 + q] = fmaf(cb, yo, -sb * z);     // y' = cb*y - sb*z
    }

    float4* o = reinterpret_cast<float4*>(out + (size_t)b * 12);
    o[0] = make_float4(res[0], res[1], res[2],  res[3]);
    o[1] = make_float4(res[4], res[5], res[6],  res[7]);
    o[2] = make_float4(res[8], res[9], res[10], res[11]);
}

extern "C" void kernel_launch(void* const* d_in, const int* in_sizes, int n_in,
                              void* d_out, int out_size) {
    const float* x   = (const float*)d_in[0];  // (B, 4)
    const float* w   = (const float*)d_in[1];  // (3, 4)
    const float* ew  = (const float*)d_in[2];  // (3, 4)
    const float* gam = (const float*)d_in[3];  // (3,)
    const float* bet = (const float*)d_in[4];  // (3,)
    float* out = (float*)d_out;                // (B, 12)

    int n = in_sizes[0] / 4;

    prep_kernel<<<1, 32>>>(w, ew, gam, bet);
    int threads = 256;
    int blocks = (n + threads - 1) / threads;
    vqc_kernel<<<blocks, threads>>>((const float4*)x, out, n);
}

// round 5
// speedup vs baseline: 2.3404x; 1.3661x over previous
#include <cuda_runtime.h>

// QnnFormerVQC: algebraically reduced 4-qubit, 3-layer VQC.
// Round-5 structure: ONE kernel. Each block computes the 30-scalar parameter
// tables into shared memory (pre-packed f32x2 broadcast constants, including
// pre-negated copies), then each thread simulates TWO batch elements packed
// into 64-bit f32x2 register pairs so every FP op is a packed fma/mul/add
// (PTX fma.rn.f32x2 -> SASS FFMA2, 2x FLOP throughput vs scalar FFMA).
//
// Verified reductions (oracle: round-3 literal kernel, rel_err 8.9e-7):
//  - RZ*RY*RX(w) -> one 2x2 complex matrix; prev layer's RX(beta) folded in.
//  - Layer-0 U applied to per-qubit (c,s) 2-vectors BEFORE tensor product.
//  - H/X/MCX diffuser block: psi_i -= (psi9+psi11+psi13+psi15)/2, i in that set
//    (reference's _apmcx swaps amplitudes 7<->15).
//  - CX-RZ(gamma)-CX chain -> 16-entry diagonal phase table.
//  - Final RX(beta2) folded into measurement: z'=cb*z+sb*y, y'=cb*y-sb*z.
// Bit convention: qubit q <-> mask (8 >> q), qubit 0 = MSB.

#define NQ 4
#define NL 3

typedef unsigned long long u64;

__device__ __forceinline__ u64 f2pack(float lo, float hi) {
    u64 r; asm("mov.b64 %0,{%1,%2};" : "=l"(r) : "f"(lo), "f"(hi)); return r;
}
__device__ __forceinline__ void f2unpack(u64 v, float& lo, float& hi) {
    asm("mov.b64 {%0,%1},%2;" : "=f"(lo), "=f"(hi) : "l"(v));
}
__device__ __forceinline__ u64 f2mul(u64 a, u64 b) {
    u64 d; asm("mul.rn.f32x2 %0,%1,%2;" : "=l"(d) : "l"(a), "l"(b)); return d;
}
__device__ __forceinline__ u64 f2add(u64 a, u64 b) {
    u64 d; asm("add.rn.f32x2 %0,%1,%2;" : "=l"(d) : "l"(a), "l"(b)); return d;
}
__device__ __forceinline__ u64 f2fma(u64 a, u64 b, u64 c) {
    u64 d; asm("fma.rn.f32x2 %0,%1,%2,%3;" : "=l"(d) : "l"(a), "l"(b), "l"(c)); return d;
}

// shared parameter tables, stored as broadcast-packed float2 (v, v)
struct SP {
    float2 u[NL][NQ][12];  // u00x,u00y,-u00y,u01x,u01y,-u01y,u10x,u10y,-u10y,u11x,u11y,-u11y
    float2 e[NL][NQ][3];   // ce, se, -se
    float2 dg[NL][16][3];  // phx, phy, -phy
    float2 mb[3];          // cos(b2), sin(b2), -sin(b2)  (FULL angle)
};

__device__ __forceinline__ float2 cmulh(float2 a, float2 b) {
    return make_float2(a.x * b.x - a.y * b.y, a.x * b.y + a.y * b.x);
}
__device__ __forceinline__ float2 caddh(float2 a, float2 b) {
    return make_float2(a.x + b.x, a.y + b.y);
}
__device__ __forceinline__ float2 bc(float v) { return make_float2(v, v); }
__device__ __forceinline__ u64 ldp(const float2* p) {
    return *reinterpret_cast<const u64*>(p);
}

__global__ void __launch_bounds__(256) vqc_kernel(const float4* __restrict__ x,
                                                  float* __restrict__ out,
                                                  const float* __restrict__ w,
                                                  const float* __restrict__ ew,
                                                  const float* __restrict__ gam,
                                                  const float* __restrict__ bet,
                                                  int n2) {
    __shared__ SP sp;
    int t = threadIdx.x;

    // ---- per-block parameter prep (parallel over first 128 threads) ----
    if (t < NL * NQ) {
        int L = t / NQ, q = t % NQ;
        float th = w[L * NQ + q];
        float c, s;
        sincosf(0.5f * th, &s, &c);
        float2 RX[2][2] = {{{c, 0.f}, {0.f, -s}}, {{0.f, -s}, {c, 0.f}}};
        float2 RY[2][2] = {{{c, 0.f}, {-s, 0.f}}, {{s, 0.f}, {c, 0.f}}};
        float2 RZ[2][2] = {{{c, -s}, {0.f, 0.f}}, {{0.f, 0.f}, {c, s}}};
        float2 T[2][2], M[2][2];
        #pragma unroll
        for (int i = 0; i < 2; i++)
            #pragma unroll
            for (int j = 0; j < 2; j++)
                T[i][j] = caddh(cmulh(RY[i][0], RX[0][j]), cmulh(RY[i][1], RX[1][j]));
        #pragma unroll
        for (int i = 0; i < 2; i++)
            #pragma unroll
            for (int j = 0; j < 2; j++)
                M[i][j] = caddh(cmulh(RZ[i][0], T[0][j]), cmulh(RZ[i][1], T[1][j]));
        if (L > 0) {  // fold previous layer's RX(beta): M_eff = M * RXb
            float cb, sb;
            sincosf(0.5f * bet[L - 1], &sb, &cb);
            float2 RXb[2][2] = {{{cb, 0.f}, {0.f, -sb}}, {{0.f, -sb}, {cb, 0.f}}};
            float2 E[2][2];
            #pragma unroll
            for (int i = 0; i < 2; i++)
                #pragma unroll
                for (int j = 0; j < 2; j++)
                    E[i][j] = caddh(cmulh(M[i][0], RXb[0][j]), cmulh(M[i][1], RXb[1][j]));
            #pragma unroll
            for (int i = 0; i < 2; i++)
                #pragma unroll
                for (int j = 0; j < 2; j++)
                    M[i][j] = E[i][j];
        }
        float2* du = sp.u[L][q];
        du[0]  = bc(M[0][0].x); du[1]  = bc(M[0][0].y); du[2]  = bc(-M[0][0].y);
        du[3]  = bc(M[0][1].x); du[4]  = bc(M[0][1].y); du[5]  = bc(-M[0][1].y);
        du[6]  = bc(M[1][0].x); du[7]  = bc(M[1][0].y); du[8]  = bc(-M[1][0].y);
        du[9]  = bc(M[1][1].x); du[10] = bc(M[1][1].y); du[11] = bc(-M[1][1].y);

        float ce, se;
        sincosf(0.5f * ew[L * NQ + q], &se, &ce);
        sp.e[L][q][0] = bc(ce); sp.e[L][q][1] = bc(se); sp.e[L][q][2] = bc(-se);
    }
    if (t >= 32 && t < 32 + NL * 16) {
        int r = t - 32;
        int L = r / 16, idx = r % 16;
        float g = gam[L];
        int k = 0;
        #pragma unroll
        for (int i = 0; i < 3; i++) {
            int bi = (idx >> (3 - i)) & 1;
            int bj = (idx >> (2 - i)) & 1;
            if (bi == bj) k++;
        }
        float ang = 0.5f * g * (float)(3 - 2 * k);
        float sa, ca;
        sincosf(ang, &sa, &ca);
        sp.dg[L][idx][0] = bc(ca); sp.dg[L][idx][1] = bc(sa); sp.dg[L][idx][2] = bc(-sa);
    }
    if (t == 96) {
        float cb, sb;
        sincosf(bet[NL - 1], &sb, &cb);  // FULL angle
        sp.mb[0] = bc(cb); sp.mb[1] = bc(sb); sp.mb[2] = bc(-sb);
    }
    __syncthreads();

    int b = blockIdx.x * blockDim.x + t;
    if (b >= n2) return;

    const u64 nOne = f2pack(-1.f, -1.f);

    // ---- load two batch elements, encode ----
    float4 x0 = x[2 * b];
    float4 x1 = x[2 * b + 1];
    float c0[4], s0[4], c1[4], s1[4];
    __sincosf(0.5f * x0.x, &s0[0], &c0[0]);
    __sincosf(0.5f * x0.y, &s0[1], &c0[1]);
    __sincosf(0.5f * x0.z, &s0[2], &c0[2]);
    __sincosf(0.5f * x0.w, &s0[3], &c0[3]);
    __sincosf(0.5f * x1.x, &s1[0], &c1[0]);
    __sincosf(0.5f * x1.y, &s1[1], &c1[1]);
    __sincosf(0.5f * x1.z, &s1[2], &c1[2]);
    __sincosf(0.5f * x1.w, &s1[3], &c1[3]);

    // layer-0 combined U applied per qubit to (c,s) (real input -> complex 2-vec)
    u64 vr[4][2], vi[4][2];
    #pragma unroll
    for (int q = 0; q < NQ; q++) {
        u64 cc = f2pack(c0[q], c1[q]);
        u64 ss = f2pack(s0[q], s1[q]);
        const float2* du = sp.u[0][q];
        u64 u00x = ldp(du + 0), u00y = ldp(du + 1);
        u64 u01x = ldp(du + 3), u01y = ldp(du + 4);
        u64 u10x = ldp(du + 6), u10y = ldp(du + 7);
        u64 u11x = ldp(du + 9), u11y = ldp(du + 10);
        vr[q][0] = f2fma(u01x, ss, f2mul(u00x, cc));
        vi[q][0] = f2fma(u01y, ss, f2mul(u00y, cc));
        vr[q][1] = f2fma(u11x, ss, f2mul(u10x, cc));
        vi[q][1] = f2fma(u11y, ss, f2mul(u10y, cc));
    }

    // tensor product: psi[b0*8+b1*4+b2*2+b3] = v0[b0]*v1[b1]*v2[b2]*v3[b3]
    u64 pr[16], pi[16];
    {
        u64 a2r[4], a2i[4], a3r[8], a3i[8];
        #pragma unroll
        for (int b0 = 0; b0 < 2; b0++)
            #pragma unroll
            for (int b1 = 0; b1 < 2; b1++) {
                int k = b0 * 2 + b1;
                u64 tt = f2mul(vi[0][b0], vi[1][b1]);
                a2r[k] = f2fma(tt, nOne, f2mul(vr[0][b0], vr[1][b1]));
                a2i[k] = f2fma(vi[0][b0], vr[1][b1], f2mul(vr[0][b0], vi[1][b1]));
            }
        #pragma unroll
        for (int k = 0; k < 4; k++)
            #pragma unroll
            for (int b2 = 0; b2 < 2; b2++) {
                int m = k * 2 + b2;
                u64 tt = f2mul(a2i[k], vi[2][b2]);
                a3r[m] = f2fma(tt, nOne, f2mul(a2r[k], vr[2][b2]));
                a3i[m] = f2fma(a2i[k], vr[2][b2], f2mul(a2r[k], vi[2][b2]));
            }
        #pragma unroll
        for (int m = 0; m < 8; m++)
            #pragma unroll
            for (int b3 = 0; b3 < 2; b3++) {
                int i = m * 2 + b3;
                u64 tt = f2mul(a3i[m], vi[3][b3]);
                pr[i] = f2fma(tt, nOne, f2mul(a3r[m], vr[3][b3]));
                pi[i] = f2fma(a3i[m], vr[3][b3], f2mul(a3r[m], vi[3][b3]));
            }
    }

    #pragma unroll
    for (int L = 0; L < NL; L++) {
        // combined single-qubit U (layer 0 already applied above)
        if (L > 0) {
            #pragma unroll
            for (int q = 0; q < NQ; q++) {
                const float2* du = sp.u[L][q];
                u64 u00x = ldp(du + 0), u00y = ldp(du + 1), nu00y = ldp(du + 2);
                u64 u01x = ldp(du + 3), u01y = ldp(du + 4), nu01y = ldp(du + 5);
                u64 u10x = ldp(du + 6), u10y = ldp(du + 7), nu10y = ldp(du + 8);
                u64 u11x = ldp(du + 9), u11y = ldp(du + 10), nu11y = ldp(du + 11);
                int mask = 8 >> q;
                #pragma unroll
                for (int i = 0; i < 16; i++) {
                    if (i & mask) continue;
                    int j = i | mask;
                    u64 ax = pr[i], ay = pi[i], dx = pr[j], dy = pi[j];
                    u64 nr = f2fma(nu01y, dy, f2fma(u01x, dx,
                                f2fma(nu00y, ay, f2mul(u00x, ax))));
                    u64 ni = f2fma(u01y, dx, f2fma(u01x, dy,
                                f2fma(u00y, ax, f2mul(u00x, ay))));
                    u64 mr = f2fma(nu11y, dy, f2fma(u11x, dx,
                                f2fma(nu10y, ay, f2mul(u10x, ax))));
                    u64 mi = f2fma(u11y, dx, f2fma(u11x, dy,
                                f2fma(u10y, ax, f2mul(u10x, ay))));
                    pr[i] = nr; pi[i] = ni; pr[j] = mr; pi[j] = mi;
                }
            }
        }

        // ring of controlled-RX: control q, target (q+1)%4
        #pragma unroll
        for (int q = 0; q < NQ; q++) {
            u64 ce = ldp(&sp.e[L][q][0]);
            u64 se = ldp(&sp.e[L][q][1]);
            u64 nse = ldp(&sp.e[L][q][2]);
            int cmask = 8 >> q;
            int tmask = 8 >> ((q + 1) & 3);
            #pragma unroll
            for (int i = 0; i < 16; i++) {
                if (!(i & cmask) || (i & tmask)) continue;
                int j = i | tmask;
                u64 ax = pr[i], ay = pi[i], dx = pr[j], dy = pi[j];
                pr[i] = f2fma(se, dy, f2mul(ce, ax));
                pi[i] = f2fma(nse, dx, f2mul(ce, ay));
                pr[j] = f2fma(ce, dx, f2mul(se, ay));
                pi[j] = f2fma(ce, dy, f2mul(nse, ax));
            }
        }

        // diffuser: psi_i -= (psi9+psi11+psi13+psi15)/2 for i in {9,11,13,15}
        {
            const u64 nh = f2pack(-0.5f, -0.5f);
            u64 srx = f2add(f2add(pr[9], pr[11]), f2add(pr[13], pr[15]));
            u64 sri = f2add(f2add(pi[9], pi[11]), f2add(pi[13], pi[15]));
            srx = f2mul(srx, nh);
            sri = f2mul(sri, nh);
            pr[9]  = f2add(pr[9],  srx); pi[9]  = f2add(pi[9],  sri);
            pr[11] = f2add(pr[11], srx); pi[11] = f2add(pi[11], sri);
            pr[13] = f2add(pr[13], srx); pi[13] = f2add(pi[13], sri);
            pr[15] = f2add(pr[15], srx); pi[15] = f2add(pi[15], sri);
        }

        // RZZ-chain diagonal phases
        #pragma unroll
        for (int i = 0; i < 16; i++) {
            u64 phx = ldp(&sp.dg[L][i][0]);
            u64 phy = ldp(&sp.dg[L][i][1]);
            u64 nphy = ldp(&sp.dg[L][i][2]);
            u64 tr = f2fma(nphy, pi[i], f2mul(phx, pr[i]));
            u64 ti = f2fma(phy, pr[i], f2mul(phx, pi[i]));
            pr[i] = tr; pi[i] = ti;
        }
        // RX(beta_L): L<2 folded into next layer's U; L==2 folded into meas.
    }

    // ---- measurement with final-RX(beta2) fold ----
    u64 cb = ldp(&sp.mb[0]);
    u64 sb = ldp(&sp.mb[1]);
    u64 nsb = ldp(&sp.mb[2]);
    u64 res[12];
    #pragma unroll
    for (int q = 0; q < NQ; q++) {
        int mask = 8 >> q;
        u64 zpos = 0ull, zneg = 0ull, xr = 0ull, yip = 0ull, yin = 0ull;
        #pragma unroll
        for (int i = 0; i < 16; i++) {
            if (i & mask) continue;
            int j = i | mask;
            u64 ax = pr[i], ay = pi[i], dx = pr[j], dy = pi[j];
            zpos = f2fma(ax, ax, zpos); zpos = f2fma(ay, ay, zpos);
            zneg = f2fma(dx, dx, zneg); zneg = f2fma(dy, dy, zneg);
            xr = f2fma(ax, dx, xr);     xr = f2fma(ay, dy, xr);
            yip = f2fma(ax, dy, yip);   yin = f2fma(ay, dx, yin);
        }
        u64 z = f2fma(zneg, nOne, zpos);
        u64 yi = f2fma(yin, nOne, yip);
        u64 xo = f2add(xr, xr);
        u64 yo = f2add(yi, yi);
        res[q]     = f2fma(cb, z, f2mul(sb, yo));   // z' = cb*z + sb*y
        res[4 + q] = xo;                            // x' = x
        res[8 + q] = f2fma(cb, yo, f2mul(nsb, z));  // y' = cb*y - sb*z
    }

    float e0[12], e1[12];
    #pragma unroll
    for (int k = 0; k < 12; k++) f2unpack(res[k], e0[k], e1[k]);

    float4* o0 = reinterpret_cast<float4*>(out + (size_t)(2 * b) * 12);
    float4* o1 = reinterpret_cast<float4*>(out + (size_t)(2 * b + 1) * 12);
    o0[0] = make_float4(e0[0], e0[1], e0[2],  e0[3]);
    o0[1] = make_float4(e0[4], e0[5], e0[6],  e0[7]);
    o0[2] = make_float4(e0[8], e0[9], e0[10], e0[11]);
    o1[0] = make_float4(e1[0], e1[1], e1[2],  e1[3]);
    o1[1] = make_float4(e1[4], e1[5], e1[6],  e1[7]);
    o1[2] = make_float4(e1[8], e1[9], e1[10], e1[11]);
}

extern "C" void kernel_launch(void* const* d_in, const int* in_sizes, int n_in,
                              void* d_out, int out_size) {
    const float* x   = (const float*)d_in[0];  // (B, 4)
    const float* w   = (const float*)d_in[1];  // (3, 4)
    const float* ew  = (const float*)d_in[2];  // (3, 4)
    const float* gam = (const float*)d_in[3];  // (3,)
    const float* bet = (const float*)d_in[4];  // (3,)
    float* out = (float*)d_out;                // (B, 12)

    int n = in_sizes[0] / 4;
    int n2 = n / 2;  // two batch elements per thread (B is even)

    int threads = 256;
    int blocks = (n2 + threads - 1) / threads;
    vqc_kernel<<<blocks, threads>>>((const float4*)x, out, w, ew, gam, bet, n2);
}

// round 6
// speedup vs baseline: 3.0550x; 1.3053x over previous
#include <cuda_runtime.h>

// QnnFormerVQC round 6: the entire batch-independent circuit (all 3 layers:
// combined RZ*RY*RX, cRX ring, diffuser, RZZ diagonal, with RX(beta0/1)
// folded into the next layer's U) is ONE fixed 16x16 complex unitary W,
// built once by a tiny prep kernel (16 threads evolve the 16 basis states
// through the verified round-4 gate sequence).
//
// Per batch element: psi = W @ p, where p = tensor_q (cos x_q/2, sin x_q/2)
// is REAL (28 muls + 512 FMA), then the verified measurement epilogue with
// RX(beta2) folded in (z' = cb*z + sb*y, y' = cb*y - sb*z, x' = x).
//
// Bit convention: qubit q <-> mask (8 >> q), qubit 0 = MSB.

#define NQ 4
#define NL 3

__device__ float2 g_W[16][16];   // W[i][j] = <i| circuit |j>
__device__ float2 g_mb;          // (cos(beta2), sin(beta2)), FULL angle

__device__ __forceinline__ float2 cmulh(float2 a, float2 b) {
    return make_float2(a.x * b.x - a.y * b.y, a.x * b.y + a.y * b.x);
}
__device__ __forceinline__ float2 caddh(float2 a, float2 b) {
    return make_float2(a.x + b.x, a.y + b.y);
}

struct PS {
    float2 U[NL][NQ][2][2];
    float  ce[NL][NQ], se[NL][NQ];
    float2 dg[NL][16];
};

__global__ void prep_kernel(const float* __restrict__ w,
                            const float* __restrict__ ew,
                            const float* __restrict__ gam,
                            const float* __restrict__ bet) {
    __shared__ PS ps;
    int t = threadIdx.x;

    // ---- parameter tables (parallel) ----
    if (t < NL * NQ) {
        int L = t / NQ, q = t % NQ;
        float th = w[L * NQ + q];
        float c, s;
        sincosf(0.5f * th, &s, &c);
        float2 RX[2][2] = {{{c, 0.f}, {0.f, -s}}, {{0.f, -s}, {c, 0.f}}};
        float2 RY[2][2] = {{{c, 0.f}, {-s, 0.f}}, {{s, 0.f}, {c, 0.f}}};
        float2 RZ[2][2] = {{{c, -s}, {0.f, 0.f}}, {{0.f, 0.f}, {c, s}}};
        float2 T[2][2], M[2][2];
        #pragma unroll
        for (int i = 0; i < 2; i++)
            #pragma unroll
            for (int j = 0; j < 2; j++)
                T[i][j] = caddh(cmulh(RY[i][0], RX[0][j]), cmulh(RY[i][1], RX[1][j]));
        #pragma unroll
        for (int i = 0; i < 2; i++)
            #pragma unroll
            for (int j = 0; j < 2; j++)
                M[i][j] = caddh(cmulh(RZ[i][0], T[0][j]), cmulh(RZ[i][1], T[1][j]));
        if (L > 0) {  // fold previous layer's RX(beta): M_eff = M * RXb
            float cb, sb;
            sincosf(0.5f * bet[L - 1], &sb, &cb);
            float2 RXb[2][2] = {{{cb, 0.f}, {0.f, -sb}}, {{0.f, -sb}, {cb, 0.f}}};
            float2 E[2][2];
            #pragma unroll
            for (int i = 0; i < 2; i++)
                #pragma unroll
                for (int j = 0; j < 2; j++)
                    E[i][j] = caddh(cmulh(M[i][0], RXb[0][j]), cmulh(M[i][1], RXb[1][j]));
            #pragma unroll
            for (int i = 0; i < 2; i++)
                #pragma unroll
                for (int j = 0; j < 2; j++)
                    M[i][j] = E[i][j];
        }
        #pragma unroll
        for (int i = 0; i < 2; i++)
            #pragma unroll
            for (int j = 0; j < 2; j++)
                ps.U[L][q][i][j] = M[i][j];

        sincosf(0.5f * ew[L * NQ + q], &ps.se[L][q], &ps.ce[L][q]);
    }
    if (t >= 16 && t < 16 + NL * 16) {
        int r = t - 16;
        int L = r / 16, idx = r % 16;
        int k = 0;
        #pragma unroll
        for (int i = 0; i < 3; i++) {
            int bi = (idx >> (3 - i)) & 1;
            int bj = (idx >> (2 - i)) & 1;
            if (bi == bj) k++;
        }
        float ang = 0.5f * gam[L] * (float)(3 - 2 * k);
        float sa, ca;
        sincosf(ang, &sa, &ca);
        ps.dg[L][idx] = make_float2(ca, sa);
    }
    if (t == 64) {
        float cb, sb;
        sincosf(bet[NL - 1], &sb, &cb);  // FULL angle
        g_mb = make_float2(cb, sb);
    }
    __syncthreads();

    // ---- evolve the 16 basis states; thread t owns column t ----
    if (t < 16) {
        float2 psi[16];
        #pragma unroll
        for (int i = 0; i < 16; i++) psi[i] = make_float2(0.f, 0.f);
        psi[t] = make_float2(1.f, 0.f);

        #pragma unroll
        for (int L = 0; L < NL; L++) {
            // combined single-qubit U per qubit
            #pragma unroll
            for (int q = 0; q < NQ; q++) {
                float2 u00 = ps.U[L][q][0][0], u01 = ps.U[L][q][0][1];
                float2 u10 = ps.U[L][q][1][0], u11 = ps.U[L][q][1][1];
                int mask = 8 >> q;
                #pragma unroll
                for (int i = 0; i < 16; i++) {
                    if (i & mask) continue;
                    int j = i | mask;
                    float2 a = psi[i], d = psi[j];
                    float nr, ni, mr, mi;
                    nr = u00.x * a.x; nr = fmaf(-u00.y, a.y, nr);
                    nr = fmaf(u01.x, d.x, nr); nr = fmaf(-u01.y, d.y, nr);
                    ni = u00.x * a.y; ni = fmaf(u00.y, a.x, ni);
                    ni = fmaf(u01.x, d.y, ni); ni = fmaf(u01.y, d.x, ni);
                    mr = u10.x * a.x; mr = fmaf(-u10.y, a.y, mr);
                    mr = fmaf(u11.x, d.x, mr); mr = fmaf(-u11.y, d.y, mr);
                    mi = u10.x * a.y; mi = fmaf(u10.y, a.x, mi);
                    mi = fmaf(u11.x, d.y, mi); mi = fmaf(u11.y, d.x, mi);
                    psi[i] = make_float2(nr, ni);
                    psi[j] = make_float2(mr, mi);
                }
            }
            // cRX ring: control q, target (q+1)%4
            #pragma unroll
            for (int q = 0; q < NQ; q++) {
                float c = ps.ce[L][q], s = ps.se[L][q];
                int cmask = 8 >> q;
                int tmask = 8 >> ((q + 1) & 3);
                #pragma unroll
                for (int i = 0; i < 16; i++) {
                    if (!(i & cmask) || (i & tmask)) continue;
                    int j = i | tmask;
                    float2 a = psi[i], d = psi[j];
                    psi[i] = make_float2(fmaf(c, a.x,  s * d.y),
                                         fmaf(c, a.y, -s * d.x));
                    psi[j] = make_float2(fmaf(s, a.y,  c * d.x),
                                         fmaf(-s, a.x, c * d.y));
                }
            }
            // diffuser: psi_i -= (psi9+psi11+psi13+psi15)/2, i in {9,11,13,15}
            {
                float sr = (psi[9].x + psi[11].x) + (psi[13].x + psi[15].x);
                float si = (psi[9].y + psi[11].y) + (psi[13].y + psi[15].y);
                sr *= 0.5f; si *= 0.5f;
                psi[9].x  -= sr; psi[9].y  -= si;
                psi[11].x -= sr; psi[11].y -= si;
                psi[13].x -= sr; psi[13].y -= si;
                psi[15].x -= sr; psi[15].y -= si;
            }
            // RZZ-chain diagonal
            #pragma unroll
            for (int i = 0; i < 16; i++) {
                float2 ph = ps.dg[L][i];
                float2 a = psi[i];
                psi[i] = make_float2(fmaf(ph.x, a.x, -ph.y * a.y),
                                     fmaf(ph.x, a.y,  ph.y * a.x));
            }
        }
        #pragma unroll
        for (int i = 0; i < 16; i++) g_W[i][t] = psi[i];
    }
}

__global__ void __launch_bounds__(256) vqc_kernel(const float4* __restrict__ x,
                                                  float* __restrict__ out,
                                                  int n) {
    __shared__ float2 Wsh[16][16];
    int t = threadIdx.x;
    if (t < 128) {
        reinterpret_cast<float4*>(&Wsh[0][0])[t] =
            reinterpret_cast<const float4*>(&g_W[0][0])[t];
    }
    __syncthreads();

    int b = blockIdx.x * blockDim.x + t;
    if (b >= n) return;

    float4 xv = x[b];
    float cq[4], sq[4];
    __sincosf(0.5f * xv.x, &sq[0], &cq[0]);
    __sincosf(0.5f * xv.y, &sq[1], &cq[1]);
    __sincosf(0.5f * xv.z, &sq[2], &cq[2]);
    __sincosf(0.5f * xv.w, &sq[3], &cq[3]);

    // p = real tensor product; p[j] picks s_q where bit (8>>q) of j is set
    float p[16];
    {
        float a01[4], a012[8];
        a01[0] = cq[0] * cq[1]; a01[1] = cq[0] * sq[1];
        a01[2] = sq[0] * cq[1]; a01[3] = sq[0] * sq[1];
        #pragma unroll
        for (int k = 0; k < 4; k++) {
            a012[2 * k]     = a01[k] * cq[2];
            a012[2 * k + 1] = a01[k] * sq[2];
        }
        #pragma unroll
        for (int m = 0; m < 8; m++) {
            p[2 * m]     = a012[m] * cq[3];
            p[2 * m + 1] = a012[m] * sq[3];
        }
    }

    // psi = W @ p  (complex x real matvec, 512 FMA)
    float2 psi[16];
    #pragma unroll
    for (int i = 0; i < 16; i++) {
        const float4* row = reinterpret_cast<const float4*>(&Wsh[i][0]);
        float re = 0.f, im = 0.f;
        #pragma unroll
        for (int jj = 0; jj < 8; jj++) {
            float4 v = row[jj];  // (W[i][2jj].x, .y, W[i][2jj+1].x, .y)
            re = fmaf(v.x, p[2 * jj], re);
            im = fmaf(v.y, p[2 * jj], im);
            re = fmaf(v.z, p[2 * jj + 1], re);
            im = fmaf(v.w, p[2 * jj + 1], im);
        }
        psi[i] = make_float2(re, im);
    }

    // measurement with final-RX(beta2) fold
    float2 mb = g_mb;
    float cb = mb.x, sb = mb.y;
    float res[12];
    #pragma unroll
    for (int q = 0; q < NQ; q++) {
        int mask = 8 >> q;
        float z = 0.f, xr = 0.f, yi = 0.f;
        #pragma unroll
        for (int i = 0; i < 16; i++) {
            if (i & mask) continue;
            int j = i | mask;
            float2 a = psi[i], d = psi[j];
            z += fmaf(a.x, a.x, a.y * a.y) - fmaf(d.x, d.x, d.y * d.y);
            xr += fmaf(a.x, d.x, a.y * d.y);    // Re(conj(a)*d)
            yi += fmaf(a.x, d.y, -a.y * d.x);   // Im(conj(a)*d)
        }
        float xo = 2.f * xr, yo = 2.f * yi;
        res[q]     = fmaf(cb, z, sb * yo);      // z' = cb*z + sb*y
        res[4 + q] = xo;                        // x' = x
        res[8 + q] = fmaf(cb, yo, -sb * z);     // y' = cb*y - sb*z
    }

    float4* o = reinterpret_cast<float4*>(out + (size_t)b * 12);
    o[0] = make_float4(res[0], res[1], res[2],  res[3]);
    o[1] = make_float4(res[4], res[5], res[6],  res[7]);
    o[2] = make_float4(res[8], res[9], res[10], res[11]);
}

extern "C" void kernel_launch(void* const* d_in, const int* in_sizes, int n_in,
                              void* d_out, int out_size) {
    const float* x   = (const float*)d_in[0];  // (B, 4)
    const float* w   = (const float*)d_in[1];  // (3, 4)
    const float* ew  = (const float*)d_in[2];  // (3, 4)
    const float* gam = (const float*)d_in[3];  // (3,)
    const float* bet = (const float*)d_in[4];  // (3,)
    float* out = (float*)d_out;                // (B, 12)

    int n = in_sizes[0] / 4;

    prep_kernel<<<1, 128>>>(w, ew, gam, bet);
    int threads = 256;
    int blocks = (n + threads - 1) / threads;
    vqc_kernel<<<blocks, threads>>>((const float4*)x, out, n);
}